// round 5
// baseline (speedup 1.0000x reference)
#include <cuda_runtime.h>
#include <cuda_bf16.h>
#include <cstdint>

// Problem constants (from reference)
#define N_NODES 100000
#define N_EDGES 1600000
#define D_FEAT  256
#define UNITS   128

// Scratch for h = x @ w  (51.2 MB, static __device__ per allocation rules)
__device__ float g_h[(size_t)N_NODES * UNITS];

// ----------------------------------------------------------------------------
// GEMM: h[m][u] = sum_k x[m][k] * w[k][u]
// Tile: TM=64 rows x full 128 cols, TK=16. 256 threads, each computes 4x8.
// ----------------------------------------------------------------------------
#define TM 64
#define TK 16

__global__ __launch_bounds__(256) void gemm_kernel(const float* __restrict__ x,
                                                   const float* __restrict__ w,
                                                   float* __restrict__ h) {
    __shared__ float sx[TM][TK];        // 64x16
    __shared__ float sw[TK][UNITS];     // 16x128

    const int block_row = blockIdx.x * TM;
    const int tid = threadIdx.x;

    // micro-tile: 4 rows x 8 cols per thread; 16x16 thread grid
    const int tr = (tid / 16) * 4;      // 0..60
    const int tc = (tid % 16) * 8;      // 0..120

    float acc[4][8];
#pragma unroll
    for (int i = 0; i < 4; i++)
#pragma unroll
        for (int j = 0; j < 8; j++) acc[i][j] = 0.0f;

    for (int k0 = 0; k0 < D_FEAT; k0 += TK) {
        // Load x tile: 64x16 floats; each thread one float4
        {
            int r = tid / 4;
            int kq = (tid % 4) * 4;
            int gr = block_row + r;
            float4 v = make_float4(0.f, 0.f, 0.f, 0.f);
            if (gr < N_NODES)
                v = *(const float4*)(x + (size_t)gr * D_FEAT + k0 + kq);
            sx[r][kq + 0] = v.x; sx[r][kq + 1] = v.y;
            sx[r][kq + 2] = v.z; sx[r][kq + 3] = v.w;
        }
        // Load w tile: 16x128 floats; each thread two float4
        {
            int r = tid / 16;
            int c = (tid % 16) * 8;
            const float* wp = w + (size_t)(k0 + r) * UNITS + c;
            float4 a = *(const float4*)(wp);
            float4 b = *(const float4*)(wp + 4);
            *(float4*)&sw[r][c]     = a;
            *(float4*)&sw[r][c + 4] = b;
        }
        __syncthreads();

#pragma unroll
        for (int kk = 0; kk < TK; kk++) {
            float a[4], b[8];
#pragma unroll
            for (int i = 0; i < 4; i++) a[i] = sx[tr + i][kk];
            float4 b0 = *(const float4*)&sw[kk][tc];
            float4 b1 = *(const float4*)&sw[kk][tc + 4];
            b[0] = b0.x; b[1] = b0.y; b[2] = b0.z; b[3] = b0.w;
            b[4] = b1.x; b[5] = b1.y; b[6] = b1.z; b[7] = b1.w;
#pragma unroll
            for (int i = 0; i < 4; i++)
#pragma unroll
                for (int j = 0; j < 8; j++) acc[i][j] += a[i] * b[j];
        }
        __syncthreads();
    }

    // Store 4x8 micro-tile as float4 pairs
#pragma unroll
    for (int i = 0; i < 4; i++) {
        int gr = block_row + tr + i;
        if (gr < N_NODES) {
            float* hp = h + (size_t)gr * UNITS + tc;
            *(float4*)(hp)     = make_float4(acc[i][0], acc[i][1], acc[i][2], acc[i][3]);
            *(float4*)(hp + 4) = make_float4(acc[i][4], acc[i][5], acc[i][6], acc[i][7]);
        }
    }
}

// ----------------------------------------------------------------------------
// Scatter: one warp per edge. Lane l handles cols [4l, 4l+4).
// out[dst] += val * h[src]  via float4 atomicAdd (sm_90+ vector atomics)
// NOTE: adj_src/adj_dst arrive as int32 (JAX x64-disabled downcasts int64).
// ----------------------------------------------------------------------------
__global__ __launch_bounds__(256) void scatter_kernel(const float* __restrict__ h,
                                                      const int* __restrict__ src,
                                                      const int* __restrict__ dst,
                                                      const float* __restrict__ vals,
                                                      float* __restrict__ out) {
    const int warp = (blockIdx.x * blockDim.x + threadIdx.x) >> 5;
    const int lane = threadIdx.x & 31;
    if (warp >= N_EDGES) return;

    const int s = src[warp];
    const int d = dst[warp];
    const float v = vals[warp];

    float4 hv = *(const float4*)(h + (size_t)s * UNITS + lane * 4);
    hv.x *= v; hv.y *= v; hv.z *= v; hv.w *= v;

    atomicAdd((float4*)(out + (size_t)d * UNITS + lane * 4), hv);
}

// ----------------------------------------------------------------------------
// Launch
// ----------------------------------------------------------------------------
extern "C" void kernel_launch(void* const* d_in, const int* in_sizes, int n_in,
                              void* d_out, int out_size) {
    const float* x    = (const float*)d_in[0];
    const float* w    = (const float*)d_in[1];
    const int*   src  = (const int*)d_in[2];
    const int*   dst  = (const int*)d_in[3];
    const float* vals = (const float*)d_in[4];
    float* out = (float*)d_out;

    // Zero output (poisoned to 0xAA by harness)
    cudaMemsetAsync(d_out, 0, (size_t)out_size * sizeof(float), 0);

    float* h;
    cudaGetSymbolAddress((void**)&h, g_h);

    // GEMM: h = x @ w
    int gemm_blocks = (N_NODES + TM - 1) / TM;
    gemm_kernel<<<gemm_blocks, 256>>>(x, w, h);

    // Scatter: 8 edges per 256-thread block
    int scatter_blocks = (N_EDGES + 7) / 8;
    scatter_kernel<<<scatter_blocks, 256>>>(h, src, dst, vals, out);
}

// round 8
// speedup vs baseline: 1.3644x; 1.3644x over previous
#include <cuda_runtime.h>
#include <cuda_bf16.h>
#include <cstdint>

// Problem constants
#define N_NODES 100000
#define N_EDGES 1600000
#define D_FEAT  256
#define UNITS   128

// Scratch for h = x @ w  (51.2 MB)
__device__ float g_h[(size_t)N_NODES * UNITS];

// ============================================================================
// Helpers
// ============================================================================
__device__ __forceinline__ uint32_t smem_u32(const void* p) {
    uint32_t a;
    asm("{ .reg .u64 t; cvta.to.shared.u64 t, %1; cvt.u32.u64 %0, t; }"
        : "=r"(a) : "l"(p));
    return a;
}

__device__ __forceinline__ uint32_t pk2(__nv_bfloat16 a, __nv_bfloat16 b) {
    uint16_t ua = *reinterpret_cast<uint16_t*>(&a);
    uint16_t ub = *reinterpret_cast<uint16_t*>(&b);
    return (uint32_t)ua | ((uint32_t)ub << 16);
}

#define LDSM_X4(r0, r1, r2, r3, addr) \
    asm volatile("ldmatrix.sync.aligned.m8n8.x4.shared.b16 {%0,%1,%2,%3}, [%4];" \
        : "=r"(r0), "=r"(r1), "=r"(r2), "=r"(r3) : "r"(addr))

#define MMA_BF16(c, a, b0, b1) \
    asm volatile("mma.sync.aligned.m16n8k16.row.col.f32.bf16.bf16.f32 " \
        "{%0,%1,%2,%3}, {%4,%5,%6,%7}, {%8,%9}, {%0,%1,%2,%3};" \
        : "+f"((c)[0]), "+f"((c)[1]), "+f"((c)[2]), "+f"((c)[3]) \
        : "r"((a)[0]), "r"((a)[1]), "r"((a)[2]), "r"((a)[3]), "r"(b0), "r"(b1))

// ============================================================================
// GEMM: h = x @ w, 2-way bf16 split on mma.sync (HMMA; base-sm_103 safe)
// CTA tile 128x128, 8 warps (4m x 2n), warp tile 32x64, K in 16 chunks of 16.
// ============================================================================
#define TILE_M  128
#define NCHUNK  16
#define A_PITCH 48      // 16 bf16 per row padded 32B->48B (conflict-free ldsm)
#define B_PITCH 528     // 256 bf16 per row padded 512B->528B (conflict-free)
#define A_BUF_SZ (TILE_M * A_PITCH)            // 6144 bytes
#define SMEM_A    0                            // 2 bufs x (hi+lo) = 4*6144 = 24576
#define SMEM_B_HI 24576                        // 128 * 528 = 67584
#define SMEM_B_LO (24576 + 67584)              // 92160
#define SMEM_TOTAL (SMEM_B_LO + 67584)         // 159744

__device__ __forceinline__ void cvt_store8(char* smem, int buf, int r, int kq,
                                           float4 v0, float4 v1) {
    float f[8] = {v0.x, v0.y, v0.z, v0.w, v1.x, v1.y, v1.z, v1.w};
    __nv_bfloat16 hi[8], lo[8];
#pragma unroll
    for (int e = 0; e < 8; e++) {
        hi[e] = __float2bfloat16(f[e]);
        lo[e] = __float2bfloat16(f[e] - __bfloat162float(hi[e]));
    }
    char* ph = smem + SMEM_A + buf * (2 * A_BUF_SZ) + r * A_PITCH + kq * 2;
    char* pl = ph + A_BUF_SZ;
    *(uint2*)(ph)     = make_uint2(pk2(hi[0], hi[1]), pk2(hi[2], hi[3]));
    *(uint2*)(ph + 8) = make_uint2(pk2(hi[4], hi[5]), pk2(hi[6], hi[7]));
    *(uint2*)(pl)     = make_uint2(pk2(lo[0], lo[1]), pk2(lo[2], lo[3]));
    *(uint2*)(pl + 8) = make_uint2(pk2(lo[4], lo[5]), pk2(lo[6], lo[7]));
}

__global__ __launch_bounds__(256, 1) void gemm_mma_kernel(const float* __restrict__ x,
                                                          const float* __restrict__ w,
                                                          float* __restrict__ h) {
    extern __shared__ char smem[];
    const uint32_t sb = smem_u32(smem);
    const int tid  = threadIdx.x;
    const int wid  = tid >> 5;
    const int lane = tid & 31;
    const int block_row = blockIdx.x * TILE_M;

    const int wm = (wid & 3) * 32;    // warp m offset within tile
    const int wn = (wid >> 2) * 64;   // warp n offset

    // ---- Convert w -> B_hi / B_lo smem, layout [n][k] (col-major B for mma) ----
    for (int idx = tid; idx < D_FEAT * UNITS; idx += 256) {
        int k = idx >> 7, n = idx & 127;
        float v = __ldg(w + idx);
        __nv_bfloat16 hi = __float2bfloat16(v);
        __nv_bfloat16 lo = __float2bfloat16(v - __bfloat162float(hi));
        *(__nv_bfloat16*)(smem + SMEM_B_HI + n * B_PITCH + k * 2) = hi;
        *(__nv_bfloat16*)(smem + SMEM_B_LO + n * B_PITCH + k * 2) = lo;
    }

    // ---- A prefetch assignment: thread covers row tid/2, 8 k-values ----
    const int pr = tid >> 1;
    const int pk = (tid & 1) * 8;
    const int grow = block_row + pr;
    const bool prow_ok = grow < N_NODES;
    const float* xrow = x + (size_t)(prow_ok ? grow : 0) * D_FEAT;

    // Preload chunk 0 into buf 0
    {
        float4 v0 = make_float4(0, 0, 0, 0), v1 = v0;
        if (prow_ok) {
            v0 = *(const float4*)(xrow + pk);
            v1 = *(const float4*)(xrow + pk + 4);
        }
        cvt_store8(smem, 0, pr, pk, v0, v1);
    }
    __syncthreads();

    float acc[2][8][4];
#pragma unroll
    for (int i = 0; i < 2; i++)
#pragma unroll
        for (int j = 0; j < 8; j++)
#pragma unroll
            for (int q = 0; q < 4; q++) acc[i][j][q] = 0.0f;

    // Hoisted per-lane fragment address components
    const uint32_t aRow = (uint32_t)(wm + (lane & 15)) * A_PITCH + ((lane >> 4) << 4);
    const uint32_t bRow = (uint32_t)(wn + (lane & 7) + ((lane >> 4) << 3)) * B_PITCH
                          + (((lane >> 3) & 1) << 4);

    for (int c = 0; c < NCHUNK; c++) {
        // Prefetch next chunk from global
        float4 v0 = make_float4(0, 0, 0, 0), v1 = v0;
        const bool pf = (c + 1 < NCHUNK);
        if (pf && prow_ok) {
            v0 = *(const float4*)(xrow + (c + 1) * 16 + pk);
            v1 = *(const float4*)(xrow + (c + 1) * 16 + pk + 4);
        }

        // A fragments (hi & lo) for both m-tiles
        const uint32_t abase = sb + SMEM_A + (c & 1) * (2 * A_BUF_SZ) + aRow;
        uint32_t ah[2][4], al[2][4];
#pragma unroll
        for (int i = 0; i < 2; i++) {
            LDSM_X4(ah[i][0], ah[i][1], ah[i][2], ah[i][3], abase + i * 16 * A_PITCH);
            LDSM_X4(al[i][0], al[i][1], al[i][2], al[i][3],
                    abase + i * 16 * A_PITCH + A_BUF_SZ);
        }

        const uint32_t bbH = sb + SMEM_B_HI + bRow + c * 32;
        const uint32_t bbL = sb + SMEM_B_LO + bRow + c * 32;
#pragma unroll
        for (int jp = 0; jp < 4; jp++) {      // n-tile pairs (2jp, 2jp+1)
            uint32_t bh[4], bl[4];
            LDSM_X4(bh[0], bh[1], bh[2], bh[3], bbH + jp * 16 * B_PITCH);
            LDSM_X4(bl[0], bl[1], bl[2], bl[3], bbL + jp * 16 * B_PITCH);
#pragma unroll
            for (int i = 0; i < 2; i++) {
                MMA_BF16(acc[i][2 * jp],     ah[i], bh[0], bh[1]);
                MMA_BF16(acc[i][2 * jp + 1], ah[i], bh[2], bh[3]);
                MMA_BF16(acc[i][2 * jp],     ah[i], bl[0], bl[1]);
                MMA_BF16(acc[i][2 * jp + 1], ah[i], bl[2], bl[3]);
                MMA_BF16(acc[i][2 * jp],     al[i], bh[0], bh[1]);
                MMA_BF16(acc[i][2 * jp + 1], al[i], bh[2], bh[3]);
            }
        }

        if (pf) cvt_store8(smem, (c + 1) & 1, pr, pk, v0, v1);
        __syncthreads();
    }

    // ---- Epilogue: c0,c1 -> row t/4; c2,c3 -> row t/4+8; cols 2*(t%4)+{0,1} ----
#pragma unroll
    for (int i = 0; i < 2; i++) {
#pragma unroll
        for (int j = 0; j < 8; j++) {
            int row0 = block_row + wm + i * 16 + (lane >> 2);
            int col  = wn + j * 8 + (lane & 3) * 2;
            if (row0 < N_NODES)
                *(float2*)(h + (size_t)row0 * UNITS + col) =
                    make_float2(acc[i][j][0], acc[i][j][1]);
            int row1 = row0 + 8;
            if (row1 < N_NODES)
                *(float2*)(h + (size_t)row1 * UNITS + col) =
                    make_float2(acc[i][j][2], acc[i][j][3]);
        }
    }
}

// ----------------------------------------------------------------------------
// Scatter: one warp per edge. Lane l handles cols [4l, 4l+4).
// ----------------------------------------------------------------------------
__global__ __launch_bounds__(256) void scatter_kernel(const float* __restrict__ h,
                                                      const int* __restrict__ src,
                                                      const int* __restrict__ dst,
                                                      const float* __restrict__ vals,
                                                      float* __restrict__ out) {
    const int warp = (blockIdx.x * blockDim.x + threadIdx.x) >> 5;
    const int lane = threadIdx.x & 31;
    if (warp >= N_EDGES) return;

    const int s = src[warp];
    const int d = dst[warp];
    const float v = vals[warp];

    float4 hv = *(const float4*)(h + (size_t)s * UNITS + lane * 4);
    hv.x *= v; hv.y *= v; hv.z *= v; hv.w *= v;

    atomicAdd((float4*)(out + (size_t)d * UNITS + lane * 4), hv);
}

// ----------------------------------------------------------------------------
// Launch
// ----------------------------------------------------------------------------
extern "C" void kernel_launch(void* const* d_in, const int* in_sizes, int n_in,
                              void* d_out, int out_size) {
    const float* x    = (const float*)d_in[0];
    const float* w    = (const float*)d_in[1];
    const int*   src  = (const int*)d_in[2];
    const int*   dst  = (const int*)d_in[3];
    const float* vals = (const float*)d_in[4];
    float* out = (float*)d_out;

    cudaMemsetAsync(d_out, 0, (size_t)out_size * sizeof(float), 0);

    float* h;
    cudaGetSymbolAddress((void**)&h, g_h);

    cudaFuncSetAttribute(gemm_mma_kernel,
                         cudaFuncAttributeMaxDynamicSharedMemorySize, SMEM_TOTAL);
    int gemm_blocks = (N_NODES + TILE_M - 1) / TILE_M;   // 782
    gemm_mma_kernel<<<gemm_blocks, 256, SMEM_TOTAL>>>(x, w, h);

    int scatter_blocks = (N_EDGES + 7) / 8;
    scatter_kernel<<<scatter_blocks, 256>>>(h, src, dst, vals, out);
}